// round 12
// baseline (speedup 1.0000x reference)
#include <cuda_runtime.h>
#include <cuda_fp16.h>
#include <math.h>
#include <stdint.h>

#define BB 64
#define TT 50
#define NN 24
#define FF 256
#define HH 256
#define G4H 1024
#define ROWS 1536
#define KCAT 512
#define SKP 40       // mma_small staging stride
#define WSTR 520     // persistent Wh cache row stride (fp16) — conflict-free
#define ASTR 136     // act staging row stride (fp16): 128 k + 8 pad
#define PTHREADS 384
#define HSTR 36      // Hs row stride (floats), 16B-aligned rows

// ---- persistent smem layout (bytes) ----
#define SM_WH    0                       // 128*WSTR*2 = 133120
#define SM_G     133120                  // 2304
#define SM_BIAS  135424                  // 512
#define SM_HS    135936                  // 96*HSTR*4 = 13824
#define SM_STAGE 149760                  // 2 x 26112 act staging (K=128 chunks)
#define BUFB     26112
#define SM_TOTAL (SM_STAGE + 2*BUFB)     // 201984 B

// ------------------ device scratch ------------------------------------------
__device__ __half g_Xh[(size_t)TT*ROWS*FF];
__device__ __half g_Xl[ROWS*FF];             // t=0 slice only (h0/c0 precision)
__device__ __half g_Ghh[2][ROWS*HH];
__device__ __half g_Ghl[ROWS*HH];            // written at t=TT-1 only
__device__ __half g_Wch[(size_t)G4H*KCAT];   // [W_ih|W_hh] gate-interleaved fp16
__device__ __half g_W1h[HH*FF], g_W1l[HH*FF];
__device__ __half g_W2h[HH*FF], g_W2l[HH*FF];
__device__ __half g_Wfh[HH*HH], g_Wfl[HH*HH];
__device__ float g_bcat[G4H];
__device__ float g_h[ROWS*HH];
__device__ float g_c[ROWS*HH];
__device__ unsigned g_bar[16];

// ------------------ helpers --------------------------------------------------
__device__ __forceinline__ float sigf(float x) { return 1.f / (1.f + __expf(-x)); }
__device__ __forceinline__ float tanh_fast(float x) {
    float ax = fabsf(x);
    float t = __expf(-2.f * ax);
    return copysignf((1.f - t) / (1.f + t), x);
}
__device__ __forceinline__ void mma16816(float* d, const unsigned* a, const unsigned* b) {
    asm volatile("mma.sync.aligned.m16n8k16.row.col.f32.f16.f16.f32 "
                 "{%0,%1,%2,%3},{%4,%5,%6,%7},{%8,%9},{%0,%1,%2,%3};"
                 : "+f"(d[0]), "+f"(d[1]), "+f"(d[2]), "+f"(d[3])
                 : "r"(a[0]), "r"(a[1]), "r"(a[2]), "r"(a[3]), "r"(b[0]), "r"(b[1]));
}
__device__ __forceinline__ void ldsm4(unsigned* r, const __half* p) {
    unsigned addr = (unsigned)__cvta_generic_to_shared(p);
    asm volatile("ldmatrix.sync.aligned.m8n8.x4.shared.b16 {%0,%1,%2,%3},[%4];"
                 : "=r"(r[0]), "=r"(r[1]), "=r"(r[2]), "=r"(r[3]) : "r"(addr));
}
__device__ __forceinline__ void cp16(uint32_t s, const void* g) {
    asm volatile("cp.async.cg.shared.global [%0], [%1], 16;" :: "r"(s), "l"(g));
}
__device__ __forceinline__ unsigned pack2h(float a, float b) {
    __half2 h = __floats2half2_rn(a, b);
    return *(unsigned*)&h;
}

// ------------------ packing ---------------------------------------------------
// packed col n = 4*j + q ; original weight row r = q*256 + j  (q: i,f,g,o)
__global__ __launch_bounds__(256)
void pack_cat(const float* __restrict__ Wih, const float* __restrict__ Whh,
              const float* __restrict__ bih, const float* __restrict__ bhh)
{
    if (blockIdx.x == 0 && threadIdx.x < 16) g_bar[threadIdx.x] = 0u;
    int idx = blockIdx.x * 256 + threadIdx.x;
    int n = idx >> 9, k = idx & 511;
    int r = (n & 3) * HH + (n >> 2);
    float v = (k < 256) ? Wih[r*256 + k] : Whh[r*256 + (k - 256)];
    g_Wch[idx] = __float2half_rn(v);
    if (k == 0) g_bcat[n] = bih[r] + bhh[r];
}
// fused hi/lo pack of W_h1, W_h2, W_fc (all 256x256)
__global__ __launch_bounds__(256)
void pack_all(const float* __restrict__ W1, const float* __restrict__ W2,
              const float* __restrict__ Wf)
{
    int b = blockIdx.x;
    int idx = (b & 255) * 256 + threadIdx.x;
    const float* W; __half *Wh, *Wl;
    if (b < 256)      { W = W1; Wh = g_W1h; Wl = g_W1l; }
    else if (b < 512) { W = W2; Wh = g_W2h; Wl = g_W2l; }
    else              { W = Wf; Wh = g_Wfh; Wl = g_Wfl; }
    float v = W[idx];
    __half hv = __float2half_rn(v);
    Wh[idx] = hv;
    Wl[idx] = __float2half_rn(v - __half2float(hv));
}

// ------------------ node-mix ---------------------------------------------------
__global__ __launch_bounds__(256)
void mix_x(const float* __restrict__ x, const float* __restrict__ G)
{
    __shared__ float xs[NN*FF];
    __shared__ float Gs[NN*NN];
    int bid = blockIdx.x, t = bid / BB, b = bid % BB;
    const float* xin = x + (size_t)(b*TT + t) * NN * FF;
    size_t ob = (size_t)bid * NN * FF;
    int tid = threadIdx.x;
    for (int i = tid; i < NN*FF; i += 256) xs[i] = xin[i];
    for (int i = tid; i < NN*NN; i += 256) Gs[i] = G[i];
    __syncthreads();
    for (int i = tid; i < NN*FF; i += 256) {
        int n = i >> 8, f = i & 255;
        float a = 0.f;
        #pragma unroll
        for (int m = 0; m < NN; ++m) a += Gs[n*NN + m] * xs[m*FF + f];
        __half hv = __float2half_rn(a);
        g_Xh[ob + i] = hv;
        if (bid < BB)
            g_Xl[ob + i] = __float2half_rn(a - __half2float(hv));
    }
}
__global__ __launch_bounds__(256)
void mix_h(const float* __restrict__ G, __half* __restrict__ oh)
{
    __shared__ float hs[NN*HH];
    __shared__ float Gs[NN*NN];
    int b = blockIdx.x, tid = threadIdx.x;
    const float* hin = g_h + (size_t)b * NN * HH;
    size_t ob = (size_t)b * NN * HH;
    for (int i = tid; i < NN*HH; i += 256) hs[i] = hin[i];
    for (int i = tid; i < NN*NN; i += 256) Gs[i] = G[i];
    __syncthreads();
    for (int i = tid; i < NN*HH; i += 256) {
        int n = i >> 8, f = i & 255;
        float a = 0.f;
        #pragma unroll
        for (int m = 0; m < NN; ++m) a += Gs[n*NN + m] * hs[m*HH + f];
        oh[ob + i] = __float2half_rn(a);
    }
}

// ------------------ small GEMM (h0/c0 fused via z, final), fp16 3-term ---------
template<int ACT>
__global__ __launch_bounds__(192)
void mma_small(const __half* __restrict__ Ah, const __half* __restrict__ Al,
               const __half* __restrict__ Bh_0, const __half* __restrict__ Bl_0,
               const float* __restrict__ bias0, float* __restrict__ Out0,
               const __half* __restrict__ Bh_1, const __half* __restrict__ Bl_1,
               const float* __restrict__ bias1, float* __restrict__ Out1)
{
    __shared__ __align__(16) char smbuf[26624];
    __half* sAh = (__half*)smbuf;
    __half* sAl = sAh + 96*SKP;
    __half* sBh = sAl + 96*SKP;
    __half* sBl = sBh + 64*SKP;
    float* Cs = (float*)smbuf;

    const __half* Bh0 = blockIdx.z ? Bh_1 : Bh_0;
    const __half* Bl0 = blockIdx.z ? Bl_1 : Bl_0;
    const float* bias = blockIdx.z ? bias1 : bias0;
    float* Out        = blockIdx.z ? Out1  : Out0;

    int tid = threadIdx.x, lane = tid & 31, warp = tid >> 5;
    int wm = warp >> 1, wn = warp & 1;
    int m0 = blockIdx.y * 96, n0 = blockIdx.x * 64;

    float acc[2][4][4] = {};
    int ar = tid >> 1, ak = (tid & 1) * 16;
    int br = tid >> 1, bk = (tid & 1) * 16;
    bool doB = tid < 128;
    uint4 pa0, pa1, pa2, pa3, pb0, pb1, pb2, pb3;

    auto fetch = [&](int kk) {
        const __half* gH = Ah + (size_t)(m0 + ar)*256 + kk + ak;
        const __half* gL = Al + (size_t)(m0 + ar)*256 + kk + ak;
        pa0 = *(const uint4*)gH; pa1 = *(const uint4*)(gH + 8);
        pa2 = *(const uint4*)gL; pa3 = *(const uint4*)(gL + 8);
        if (doB) {
            const __half* gBh = Bh0 + (size_t)(n0 + br)*256 + kk + bk;
            const __half* gBl = Bl0 + (size_t)(n0 + br)*256 + kk + bk;
            pb0 = *(const uint4*)gBh; pb1 = *(const uint4*)(gBh + 8);
            pb2 = *(const uint4*)gBl; pb3 = *(const uint4*)(gBl + 8);
        }
    };
    fetch(0);
    for (int kk = 0; kk < 256; kk += 32) {
        *(uint4*)&sAh[ar*SKP + ak]     = pa0;
        *(uint4*)&sAh[ar*SKP + ak + 8] = pa1;
        *(uint4*)&sAl[ar*SKP + ak]     = pa2;
        *(uint4*)&sAl[ar*SKP + ak + 8] = pa3;
        if (doB) {
            *(uint4*)&sBh[br*SKP + bk]     = pb0;
            *(uint4*)&sBh[br*SKP + bk + 8] = pb1;
            *(uint4*)&sBl[br*SKP + bk]     = pb2;
            *(uint4*)&sBl[br*SKP + bk + 8] = pb3;
        }
        __syncthreads();
        if (kk + 32 < 256) fetch(kk + 32);
        #pragma unroll
        for (int kq = 0; kq < 32; kq += 16) {
            unsigned ah[2][4], al[2][4], bh[4][2], bl[4][2];
            #pragma unroll
            for (int i = 0; i < 2; ++i) {
                int row = wm*32 + i*16 + (lane & 15);
                int col = kq + ((lane >> 4) << 3);
                ldsm4(ah[i], &sAh[row*SKP + col]);
                ldsm4(al[i], &sAl[row*SKP + col]);
            }
            {
                int g = lane >> 3, r = lane & 7;
                int nrow = wn*32 + ((g >> 1) << 3) + r;
                int kcol = kq + ((g & 1) << 3);
                unsigned t0[4], t1[4], u0[4], u1[4];
                ldsm4(t0, &sBh[(nrow)      * SKP + kcol]);
                ldsm4(t1, &sBh[(nrow + 16) * SKP + kcol]);
                ldsm4(u0, &sBl[(nrow)      * SKP + kcol]);
                ldsm4(u1, &sBl[(nrow + 16) * SKP + kcol]);
                bh[0][0]=t0[0]; bh[0][1]=t0[1]; bh[1][0]=t0[2]; bh[1][1]=t0[3];
                bh[2][0]=t1[0]; bh[2][1]=t1[1]; bh[3][0]=t1[2]; bh[3][1]=t1[3];
                bl[0][0]=u0[0]; bl[0][1]=u0[1]; bl[1][0]=u0[2]; bl[1][1]=u0[3];
                bl[2][0]=u1[0]; bl[2][1]=u1[1]; bl[3][0]=u1[2]; bl[3][1]=u1[3];
            }
            #pragma unroll
            for (int i = 0; i < 2; ++i)
                #pragma unroll
                for (int j = 0; j < 4; ++j) {
                    mma16816(acc[i][j], ah[i], bh[j]);
                    mma16816(acc[i][j], al[i], bh[j]);
                    mma16816(acc[i][j], ah[i], bl[j]);
                }
        }
        __syncthreads();
    }
    #pragma unroll
    for (int i = 0; i < 2; ++i) {
        int r = wm*32 + i*16 + (lane >> 2);
        #pragma unroll
        for (int j = 0; j < 4; ++j) {
            int cc = wn*32 + j*8 + (lane & 3)*2;
            Cs[r*68 + cc]         = acc[i][j][0];
            Cs[r*68 + cc + 1]     = acc[i][j][1];
            Cs[(r+8)*68 + cc]     = acc[i][j][2];
            Cs[(r+8)*68 + cc + 1] = acc[i][j][3];
        }
    }
    __syncthreads();
    for (int idx = tid; idx < 96*64; idx += 192) {
        int r = idx >> 6, cc = idx & 63;
        float v = Cs[r*68 + cc] + bias[n0 + cc];
        if (ACT) v = tanh_fast(v);
        Out[(size_t)(m0 + r)*256 + n0 + cc] = v;
    }
}

// ------------------ persistent pure-fp16 scan (K=128 chunks) --------------------
__global__ __launch_bounds__(PTHREADS, 1)
void lstm_persist(const __half* __restrict__ Xh, const __half* __restrict__ Wh,
                  const float* __restrict__ bias, const float* __restrict__ Gmat,
                  const float* __restrict__ Cinit,
                  __half* __restrict__ GhH, __half* __restrict__ GhL)
{
    extern __shared__ __align__(16) char sm[];
    __half* sWh  = (__half*)(sm + SM_WH);
    float* sG    = (float*)(sm + SM_G);
    float* sBias = (float*)(sm + SM_BIAS);
    float* Hs    = (float*)(sm + SM_HS);
    const uint32_t smu = (uint32_t)__cvta_generic_to_shared(sm);

    const int tid = threadIdx.x, lane = tid & 31, warp = tid >> 5;
    const int wr = warp >> 2, wg = warp & 3;
    const int grp = blockIdx.x >> 3, nc = blockIdx.x & 7;
    const int m0 = grp*96, n0 = nc*128, u0 = nc*32;
    const int p = lane & 1;

    // one-time: Wh cache, G, bias, c (fragment layout)
    for (int e = tid; e < 128*64; e += PTHREADS) {
        int r = e >> 6, kq = (e & 63) * 8;
        *(uint4*)&sWh[r*WSTR + kq] = *(const uint4*)(Wh + (size_t)(n0 + r)*KCAT + kq);
    }
    for (int i = tid; i < NN*NN; i += PTHREADS) sG[i] = Gmat[i];
    if (tid < 128) sBias[tid] = bias[n0 + tid];
    float creg[8];
    #pragma unroll
    for (int i = 0; i < 2; ++i)
        #pragma unroll
        for (int j = 0; j < 4; ++j) {
            int row = wr*32 + i*16 + (lane >> 2) + 8*p;
            int uu  = wg*8 + 2*j + ((lane & 3) >> 1);
            creg[i*4 + j] = Cinit[(m0 + row)*HH + u0 + uu];
        }
    __syncthreads();

    const int ar = tid >> 2, ak = (tid & 3) * 32;   // 96 rows x 128 k staging
    // epilogue node-mix mapping: one row, octet of units per thread
    const int er = tid >> 2, eu = (tid & 3) * 8;
    const int elb = er / NN, en = er - elb * NN;

    auto issue = [&](const __half* src, int kk, int buf) {
        uint32_t sb = smu + SM_STAGE + buf*BUFB + (ar*ASTR + ak)*2;
        const __half* gp = src + (size_t)(m0 + ar)*256 + kk + ak;
        cp16(sb,      gp);
        cp16(sb + 16, gp + 8);
        cp16(sb + 32, gp + 16);
        cp16(sb + 48, gp + 24);
        asm volatile("cp.async.commit_group;");
    };

    issue(Xh, 0, 0);   // prefetch t=0 phase-1 chunk0

    for (int t = 0; t < TT; ++t) {
        const int pi = t & 1, po = pi ^ 1;
        const __half* XhT = Xh + (size_t)t*ROWS*FF;
        const __half* GhHp = GhH + (size_t)pi*ROWS*HH;

        float acc[2][4][4];
        #pragma unroll
        for (int i = 0; i < 2; ++i)
            #pragma unroll
            for (int j = 0; j < 4; ++j)
                #pragma unroll
                for (int e = 0; e < 4; ++e) acc[i][j][e] = 0.f;

        auto compute = [&](int kw, int buf) {   // kw = global k base into sWh
            const __half* sB = (const __half*)(sm + SM_STAGE + buf*BUFB);
            #pragma unroll
            for (int kq = 0; kq < 128; kq += 16) {
                unsigned a[2][4], w[4][2];
                #pragma unroll
                for (int i = 0; i < 2; ++i) {
                    int row = wr*32 + i*16 + (lane & 15);
                    int col = kq + ((lane >> 4) << 3);
                    ldsm4(a[i], &sB[row*ASTR + col]);
                }
                #pragma unroll
                for (int j2 = 0; j2 < 2; ++j2) {
                    int g = lane >> 3, r = lane & 7;
                    int grow = wg*32 + j2*16 + ((g >> 1) << 3) + r;
                    int kcol = kw + kq + ((g & 1) << 3);
                    unsigned tw[4];
                    ldsm4(tw, &sWh[grow*WSTR + kcol]);
                    w[j2*2][0]   = tw[0]; w[j2*2][1]   = tw[1];
                    w[j2*2+1][0] = tw[2]; w[j2*2+1][1] = tw[3];
                }
                #pragma unroll
                for (int i = 0; i < 2; ++i)
                    #pragma unroll
                    for (int j = 0; j < 4; ++j)
                        mma16816(acc[i][j], a[i], w[j]);
            }
        };

        // phase 1: k [0,256) from x(t), 2 chunks of 128
        asm volatile("cp.async.wait_group 0;" ::: "memory");
        __syncthreads();
        issue(XhT, 128, 1);
        compute(0, 0);
        asm volatile("cp.async.wait_group 0;" ::: "memory");
        __syncthreads();
        compute(128, 1);

        // wait for all 8 peers to have published Gh(t)
        if (t > 0) {
            if (tid == 0) {
                unsigned v, tgt = 8u * (unsigned)t;
                while (1) {
                    asm volatile("ld.acquire.gpu.global.u32 %0, [%1];"
                                 : "=r"(v) : "l"(&g_bar[grp]) : "memory");
                    if (v >= tgt) break;
                    __nanosleep(32);
                }
            }
            __syncthreads();
        }
        // phase 2: k [256,512) from Gh(t), 2 chunks of 128
        issue(GhHp, 0, 0);
        asm volatile("cp.async.wait_group 0;" ::: "memory");
        __syncthreads();
        issue(GhHp, 128, 1);
        compute(256, 0);
        asm volatile("cp.async.wait_group 0;" ::: "memory");
        __syncthreads();
        compute(384, 1);

        // prefetch next step's phase-1 chunk0 during epilogue (buf0 is free:
        // its last reader compute(256,0) completed before the last sync)
        if (t + 1 < TT) issue(XhT + ROWS*FF, 0, 0);

        // ---- fused epilogue: shfl-quad + LSTM cell (c in regs) ----
        #pragma unroll
        for (int i = 0; i < 2; ++i)
            #pragma unroll
            for (int j = 0; j < 4; ++j) {
                float d0 = acc[i][j][0], d1 = acc[i][j][1];
                float d2 = acc[i][j][2], d3 = acc[i][j][3];
                float s0 = __shfl_xor_sync(0xffffffffu, p ? d0 : d2, 1);
                float s1 = __shfl_xor_sync(0xffffffffu, p ? d1 : d3, 1);
                float qi = p ? s0 : d0, qf = p ? s1 : d1;
                float qg = p ? d2 : s0, qo = p ? d3 : s1;
                int row = wr*32 + i*16 + (lane >> 2) + 8*p;
                int uu  = wg*8 + 2*j + ((lane & 3) >> 1);
                float4 bv = *(const float4*)&sBias[4*uu];
                float vi = sigf(qi + bv.x);
                float vf = sigf(qf + bv.y);
                float vg = tanh_fast(qg + bv.z);
                float vo = sigf(qo + bv.w);
                float cv = vf * creg[i*4 + j] + vi * vg;
                creg[i*4 + j] = cv;
                Hs[row*HSTR + uu] = vo * tanh_fast(cv);
            }
        __syncthreads();
        // node-mix fresh h -> Gh(po): one row x 8 units per thread, vectorized
        {
            float4 A = {0.f, 0.f, 0.f, 0.f}, B4 = {0.f, 0.f, 0.f, 0.f};
            const float* gr = &sG[en*NN];
            #pragma unroll
            for (int m = 0; m < NN; ++m) {
                float g = gr[m];
                const float4* hp = (const float4*)&Hs[(elb*NN + m)*HSTR + eu];
                float4 h0 = hp[0], h1 = hp[1];
                A.x += g*h0.x; A.y += g*h0.y; A.z += g*h0.z; A.w += g*h0.w;
                B4.x += g*h1.x; B4.y += g*h1.y; B4.z += g*h1.z; B4.w += g*h1.w;
            }
            uint4 hv;
            hv.x = pack2h(A.x, A.y);  hv.y = pack2h(A.z, A.w);
            hv.z = pack2h(B4.x, B4.y); hv.w = pack2h(B4.z, B4.w);
            size_t off = (size_t)(m0 + er)*HH + u0 + eu;
            *(uint4*)(GhH + (size_t)po*ROWS*HH + off) = hv;
            if (t == TT - 1) {   // lo residual for final fc GEMM
                const __half* hb = (const __half*)&hv;
                float lo[8] = {
                    A.x  - __half2float(hb[0]), A.y  - __half2float(hb[1]),
                    A.z  - __half2float(hb[2]), A.w  - __half2float(hb[3]),
                    B4.x - __half2float(hb[4]), B4.y - __half2float(hb[5]),
                    B4.z - __half2float(hb[6]), B4.w - __half2float(hb[7]) };
                uint4 lv;
                lv.x = pack2h(lo[0], lo[1]); lv.y = pack2h(lo[2], lo[3]);
                lv.z = pack2h(lo[4], lo[5]); lv.w = pack2h(lo[6], lo[7]);
                *(uint4*)(GhL + off) = lv;
            }
        }
        __syncthreads();
        if (tid == 0)
            asm volatile("red.release.gpu.global.add.u32 [%0], %1;"
                         :: "l"(&g_bar[grp]), "r"(1u) : "memory");
    }
}

// ---------------------------------------------------------------------------
extern "C" void kernel_launch(void* const* d_in, const int* in_sizes, int n_in,
                              void* d_out, int out_size)
{
    const float* x    = (const float*)d_in[0];
    const float* G    = (const float*)d_in[1];
    const float* W_ih = (const float*)d_in[2];
    const float* b_ih = (const float*)d_in[3];
    const float* W_hh = (const float*)d_in[4];
    const float* b_hh = (const float*)d_in[5];
    const float* W_h1 = (const float*)d_in[6];
    const float* b_h1 = (const float*)d_in[7];
    const float* W_h2 = (const float*)d_in[8];
    const float* b_h2 = (const float*)d_in[9];
    const float* W_fc = (const float*)d_in[10];
    const float* b_fc = (const float*)d_in[11];
    float* out = (float*)d_out;

    __half *Xh, *Xl, *Ghh, *Ghl, *Wch, *W1h, *W1l, *W2h, *W2l, *Wfh, *Wfl;
    float *bcat, *h, *c;
    cudaGetSymbolAddress((void**)&Xh,  g_Xh);
    cudaGetSymbolAddress((void**)&Xl,  g_Xl);
    cudaGetSymbolAddress((void**)&Ghh, g_Ghh);
    cudaGetSymbolAddress((void**)&Ghl, g_Ghl);
    cudaGetSymbolAddress((void**)&Wch, g_Wch);
    cudaGetSymbolAddress((void**)&W1h, g_W1h);
    cudaGetSymbolAddress((void**)&W1l, g_W1l);
    cudaGetSymbolAddress((void**)&W2h, g_W2h);
    cudaGetSymbolAddress((void**)&W2l, g_W2l);
    cudaGetSymbolAddress((void**)&Wfh, g_Wfh);
    cudaGetSymbolAddress((void**)&Wfl, g_Wfl);
    cudaGetSymbolAddress((void**)&bcat, g_bcat);
    cudaGetSymbolAddress((void**)&h,   g_h);
    cudaGetSymbolAddress((void**)&c,   g_c);

    cudaFuncSetAttribute(lstm_persist, cudaFuncAttributeMaxDynamicSharedMemorySize, SM_TOTAL);

    // prep
    mix_x<<<BB*TT, 256>>>(x, G);
    pack_cat<<<(G4H*KCAT)/256, 256>>>(W_ih, W_hh, b_ih, b_hh);
    pack_all<<<768, 256>>>(W_h1, W_h2, W_fc);

    // h0 and c0 concurrently (z selects weight/bias/output)
    mma_small<0><<<dim3(4, 16, 2), 192>>>(Xh, Xl,
                                          W1h, W1l, b_h1, h,
                                          W2h, W2l, b_h2, c);
    mix_h<<<BB, 256>>>(G, Ghh);   // Gh(0) hi -> buffer 0

    // persistent pure-fp16 scan (50 steps, K=128 chunks)
    lstm_persist<<<128, PTHREADS, SM_TOTAL>>>(Xh, Wch, bcat, G, c, Ghh, Ghl);

    // output: tanh((G h) @ W_fc^T + b_fc); after 50 steps Gh is in buffer 0
    mma_small<1><<<dim3(4, 16, 1), 192>>>(Ghh, Ghl,
                                          Wfh, Wfl, b_fc, out,
                                          Wfh, Wfl, b_fc, out);
}

// round 13
// speedup vs baseline: 1.0568x; 1.0568x over previous
#include <cuda_runtime.h>
#include <cuda_fp16.h>
#include <math.h>
#include <stdint.h>

#define BB 64
#define TT 50
#define NN 24
#define FF 256
#define HH 256
#define G4H 1024
#define ROWS 1536
#define KCAT 512
#define SKP 40       // mma_small staging stride
#define WSTR 520     // persistent Wh cache row stride (fp16) — conflict-free
#define ASTR 72      // act staging row stride (fp16) — conflict-free
#define PTHREADS 384
#define HSTR 36      // Hs row stride (floats), 16B-aligned rows

// ---- persistent smem layout (bytes) ----
#define SM_WH    0                       // 128*WSTR*2 = 133120
#define SM_G     133120                  // 2304
#define SM_BIAS  135424                  // 512
#define SM_HS    135936                  // 96*HSTR*4 = 13824
#define SM_STAGE 149760                  // 4 x 13824 act staging (depth-2 pipe)
#define BUFB     13824
#define SM_TOTAL (SM_STAGE + 4*BUFB)     // 205056 B

// ------------------ device scratch ------------------------------------------
__device__ __half g_Xh[(size_t)TT*ROWS*FF];
__device__ __half g_Xl[ROWS*FF];             // t=0 slice only (h0/c0 precision)
__device__ __half g_Ghh[2][ROWS*HH];
__device__ __half g_Ghl[ROWS*HH];            // written at t=TT-1 only
__device__ __half g_Wch[(size_t)G4H*KCAT];   // [W_ih|W_hh] gate-interleaved fp16
__device__ __half g_W1h[HH*FF], g_W1l[HH*FF];
__device__ __half g_W2h[HH*FF], g_W2l[HH*FF];
__device__ __half g_Wfh[HH*HH], g_Wfl[HH*HH];
__device__ float g_bcat[G4H];
__device__ float g_h[ROWS*HH];
__device__ float g_c[ROWS*HH];
__device__ unsigned g_bar[16];

// ------------------ helpers --------------------------------------------------
__device__ __forceinline__ float sigf(float x) { return 1.f / (1.f + __expf(-x)); }
__device__ __forceinline__ float tanh_fast(float x) {
    float ax = fabsf(x);
    float t = __expf(-2.f * ax);
    return copysignf((1.f - t) / (1.f + t), x);
}
__device__ __forceinline__ void mma16816(float* d, const unsigned* a, const unsigned* b) {
    asm volatile("mma.sync.aligned.m16n8k16.row.col.f32.f16.f16.f32 "
                 "{%0,%1,%2,%3},{%4,%5,%6,%7},{%8,%9},{%0,%1,%2,%3};"
                 : "+f"(d[0]), "+f"(d[1]), "+f"(d[2]), "+f"(d[3])
                 : "r"(a[0]), "r"(a[1]), "r"(a[2]), "r"(a[3]), "r"(b[0]), "r"(b[1]));
}
__device__ __forceinline__ void ldsm4(unsigned* r, const __half* p) {
    unsigned addr = (unsigned)__cvta_generic_to_shared(p);
    asm volatile("ldmatrix.sync.aligned.m8n8.x4.shared.b16 {%0,%1,%2,%3},[%4];"
                 : "=r"(r[0]), "=r"(r[1]), "=r"(r[2]), "=r"(r[3]) : "r"(addr));
}
__device__ __forceinline__ void cp16(uint32_t s, const void* g) {
    asm volatile("cp.async.cg.shared.global [%0], [%1], 16;" :: "r"(s), "l"(g));
}
#define CP_COMMIT() asm volatile("cp.async.commit_group;")
#define CP_WAIT0()  asm volatile("cp.async.wait_group 0;" ::: "memory")
#define CP_WAIT1()  asm volatile("cp.async.wait_group 1;" ::: "memory")
__device__ __forceinline__ unsigned pack2h(float a, float b) {
    __half2 h = __floats2half2_rn(a, b);
    return *(unsigned*)&h;
}

// ------------------ packing ---------------------------------------------------
// packed col n = 4*j + q ; original weight row r = q*256 + j  (q: i,f,g,o)
__global__ __launch_bounds__(256)
void pack_cat(const float* __restrict__ Wih, const float* __restrict__ Whh,
              const float* __restrict__ bih, const float* __restrict__ bhh)
{
    if (blockIdx.x == 0 && threadIdx.x < 16) g_bar[threadIdx.x] = 0u;
    int idx = blockIdx.x * 256 + threadIdx.x;
    int n = idx >> 9, k = idx & 511;
    int r = (n & 3) * HH + (n >> 2);
    float v = (k < 256) ? Wih[r*256 + k] : Whh[r*256 + (k - 256)];
    g_Wch[idx] = __float2half_rn(v);
    if (k == 0) g_bcat[n] = bih[r] + bhh[r];
}
// fused hi/lo pack of W_h1, W_h2, W_fc (all 256x256)
__global__ __launch_bounds__(256)
void pack_all(const float* __restrict__ W1, const float* __restrict__ W2,
              const float* __restrict__ Wf)
{
    int b = blockIdx.x;
    int idx = (b & 255) * 256 + threadIdx.x;
    const float* W; __half *Wh, *Wl;
    if (b < 256)      { W = W1; Wh = g_W1h; Wl = g_W1l; }
    else if (b < 512) { W = W2; Wh = g_W2h; Wl = g_W2l; }
    else              { W = Wf; Wh = g_Wfh; Wl = g_Wfl; }
    float v = W[idx];
    __half hv = __float2half_rn(v);
    Wh[idx] = hv;
    Wl[idx] = __float2half_rn(v - __half2float(hv));
}

// ------------------ node-mix ---------------------------------------------------
__global__ __launch_bounds__(256)
void mix_x(const float* __restrict__ x, const float* __restrict__ G)
{
    __shared__ float xs[NN*FF];
    __shared__ float Gs[NN*NN];
    int bid = blockIdx.x, t = bid / BB, b = bid % BB;
    const float* xin = x + (size_t)(b*TT + t) * NN * FF;
    size_t ob = (size_t)bid * NN * FF;
    int tid = threadIdx.x;
    for (int i = tid; i < NN*FF; i += 256) xs[i] = xin[i];
    for (int i = tid; i < NN*NN; i += 256) Gs[i] = G[i];
    __syncthreads();
    for (int i = tid; i < NN*FF; i += 256) {
        int n = i >> 8, f = i & 255;
        float a = 0.f;
        #pragma unroll
        for (int m = 0; m < NN; ++m) a += Gs[n*NN + m] * xs[m*FF + f];
        __half hv = __float2half_rn(a);
        g_Xh[ob + i] = hv;
        if (bid < BB)
            g_Xl[ob + i] = __float2half_rn(a - __half2float(hv));
    }
}
__global__ __launch_bounds__(256)
void mix_h(const float* __restrict__ G, __half* __restrict__ oh)
{
    __shared__ float hs[NN*HH];
    __shared__ float Gs[NN*NN];
    int b = blockIdx.x, tid = threadIdx.x;
    const float* hin = g_h + (size_t)b * NN * HH;
    size_t ob = (size_t)b * NN * HH;
    for (int i = tid; i < NN*HH; i += 256) hs[i] = hin[i];
    for (int i = tid; i < NN*NN; i += 256) Gs[i] = G[i];
    __syncthreads();
    for (int i = tid; i < NN*HH; i += 256) {
        int n = i >> 8, f = i & 255;
        float a = 0.f;
        #pragma unroll
        for (int m = 0; m < NN; ++m) a += Gs[n*NN + m] * hs[m*HH + f];
        oh[ob + i] = __float2half_rn(a);
    }
}

// ------------------ small GEMM (h0/c0 fused via z, final), fp16 3-term ---------
template<int ACT>
__global__ __launch_bounds__(192)
void mma_small(const __half* __restrict__ Ah, const __half* __restrict__ Al,
               const __half* __restrict__ Bh_0, const __half* __restrict__ Bl_0,
               const float* __restrict__ bias0, float* __restrict__ Out0,
               const __half* __restrict__ Bh_1, const __half* __restrict__ Bl_1,
               const float* __restrict__ bias1, float* __restrict__ Out1)
{
    __shared__ __align__(16) char smbuf[26624];
    __half* sAh = (__half*)smbuf;
    __half* sAl = sAh + 96*SKP;
    __half* sBh = sAl + 96*SKP;
    __half* sBl = sBh + 64*SKP;
    float* Cs = (float*)smbuf;

    const __half* Bh0 = blockIdx.z ? Bh_1 : Bh_0;
    const __half* Bl0 = blockIdx.z ? Bl_1 : Bl_0;
    const float* bias = blockIdx.z ? bias1 : bias0;
    float* Out        = blockIdx.z ? Out1  : Out0;

    int tid = threadIdx.x, lane = tid & 31, warp = tid >> 5;
    int wm = warp >> 1, wn = warp & 1;
    int m0 = blockIdx.y * 96, n0 = blockIdx.x * 64;

    float acc[2][4][4] = {};
    int ar = tid >> 1, ak = (tid & 1) * 16;
    int br = tid >> 1, bk = (tid & 1) * 16;
    bool doB = tid < 128;
    uint4 pa0, pa1, pa2, pa3, pb0, pb1, pb2, pb3;

    auto fetch = [&](int kk) {
        const __half* gH = Ah + (size_t)(m0 + ar)*256 + kk + ak;
        const __half* gL = Al + (size_t)(m0 + ar)*256 + kk + ak;
        pa0 = *(const uint4*)gH; pa1 = *(const uint4*)(gH + 8);
        pa2 = *(const uint4*)gL; pa3 = *(const uint4*)(gL + 8);
        if (doB) {
            const __half* gBh = Bh0 + (size_t)(n0 + br)*256 + kk + bk;
            const __half* gBl = Bl0 + (size_t)(n0 + br)*256 + kk + bk;
            pb0 = *(const uint4*)gBh; pb1 = *(const uint4*)(gBh + 8);
            pb2 = *(const uint4*)gBl; pb3 = *(const uint4*)(gBl + 8);
        }
    };
    fetch(0);
    for (int kk = 0; kk < 256; kk += 32) {
        *(uint4*)&sAh[ar*SKP + ak]     = pa0;
        *(uint4*)&sAh[ar*SKP + ak + 8] = pa1;
        *(uint4*)&sAl[ar*SKP + ak]     = pa2;
        *(uint4*)&sAl[ar*SKP + ak + 8] = pa3;
        if (doB) {
            *(uint4*)&sBh[br*SKP + bk]     = pb0;
            *(uint4*)&sBh[br*SKP + bk + 8] = pb1;
            *(uint4*)&sBl[br*SKP + bk]     = pb2;
            *(uint4*)&sBl[br*SKP + bk + 8] = pb3;
        }
        __syncthreads();
        if (kk + 32 < 256) fetch(kk + 32);
        #pragma unroll
        for (int kq = 0; kq < 32; kq += 16) {
            unsigned ah[2][4], al[2][4], bh[4][2], bl[4][2];
            #pragma unroll
            for (int i = 0; i < 2; ++i) {
                int row = wm*32 + i*16 + (lane & 15);
                int col = kq + ((lane >> 4) << 3);
                ldsm4(ah[i], &sAh[row*SKP + col]);
                ldsm4(al[i], &sAl[row*SKP + col]);
            }
            {
                int g = lane >> 3, r = lane & 7;
                int nrow = wn*32 + ((g >> 1) << 3) + r;
                int kcol = kq + ((g & 1) << 3);
                unsigned t0[4], t1[4], u0[4], u1[4];
                ldsm4(t0, &sBh[(nrow)      * SKP + kcol]);
                ldsm4(t1, &sBh[(nrow + 16) * SKP + kcol]);
                ldsm4(u0, &sBl[(nrow)      * SKP + kcol]);
                ldsm4(u1, &sBl[(nrow + 16) * SKP + kcol]);
                bh[0][0]=t0[0]; bh[0][1]=t0[1]; bh[1][0]=t0[2]; bh[1][1]=t0[3];
                bh[2][0]=t1[0]; bh[2][1]=t1[1]; bh[3][0]=t1[2]; bh[3][1]=t1[3];
                bl[0][0]=u0[0]; bl[0][1]=u0[1]; bl[1][0]=u0[2]; bl[1][1]=u0[3];
                bl[2][0]=u1[0]; bl[2][1]=u1[1]; bl[3][0]=u1[2]; bl[3][1]=u1[3];
            }
            #pragma unroll
            for (int i = 0; i < 2; ++i)
                #pragma unroll
                for (int j = 0; j < 4; ++j) {
                    mma16816(acc[i][j], ah[i], bh[j]);
                    mma16816(acc[i][j], al[i], bh[j]);
                    mma16816(acc[i][j], ah[i], bl[j]);
                }
        }
        __syncthreads();
    }
    #pragma unroll
    for (int i = 0; i < 2; ++i) {
        int r = wm*32 + i*16 + (lane >> 2);
        #pragma unroll
        for (int j = 0; j < 4; ++j) {
            int cc = wn*32 + j*8 + (lane & 3)*2;
            Cs[r*68 + cc]         = acc[i][j][0];
            Cs[r*68 + cc + 1]     = acc[i][j][1];
            Cs[(r+8)*68 + cc]     = acc[i][j][2];
            Cs[(r+8)*68 + cc + 1] = acc[i][j][3];
        }
    }
    __syncthreads();
    for (int idx = tid; idx < 96*64; idx += 192) {
        int r = idx >> 6, cc = idx & 63;
        float v = Cs[r*68 + cc] + bias[n0 + cc];
        if (ACT) v = tanh_fast(v);
        Out[(size_t)(m0 + r)*256 + n0 + cc] = v;
    }
}

// ------------------ persistent pure-fp16 scan (depth-2 cp.async pipe) -----------
__global__ __launch_bounds__(PTHREADS, 1)
void lstm_persist(const __half* __restrict__ Xh, const __half* __restrict__ Wh,
                  const float* __restrict__ bias, const float* __restrict__ Gmat,
                  const float* __restrict__ Cinit,
                  __half* __restrict__ GhH, __half* __restrict__ GhL)
{
    extern __shared__ __align__(16) char sm[];
    __half* sWh  = (__half*)(sm + SM_WH);
    float* sG    = (float*)(sm + SM_G);
    float* sBias = (float*)(sm + SM_BIAS);
    float* Hs    = (float*)(sm + SM_HS);
    const uint32_t smu = (uint32_t)__cvta_generic_to_shared(sm);

    const int tid = threadIdx.x, lane = tid & 31, warp = tid >> 5;
    const int wr = warp >> 2, wg = warp & 3;
    const int grp = blockIdx.x >> 3, nc = blockIdx.x & 7;
    const int m0 = grp*96, n0 = nc*128, u0 = nc*32;
    const int p = lane & 1;

    // one-time: Wh cache, G, bias, c (fragment layout)
    for (int e = tid; e < 128*64; e += PTHREADS) {
        int r = e >> 6, kq = (e & 63) * 8;
        *(uint4*)&sWh[r*WSTR + kq] = *(const uint4*)(Wh + (size_t)(n0 + r)*KCAT + kq);
    }
    for (int i = tid; i < NN*NN; i += PTHREADS) sG[i] = Gmat[i];
    if (tid < 128) sBias[tid] = bias[n0 + tid];
    float creg[8];
    #pragma unroll
    for (int i = 0; i < 2; ++i)
        #pragma unroll
        for (int j = 0; j < 4; ++j) {
            int row = wr*32 + i*16 + (lane >> 2) + 8*p;
            int uu  = wg*8 + 2*j + ((lane & 3) >> 1);
            creg[i*4 + j] = Cinit[(m0 + row)*HH + u0 + uu];
        }
    __syncthreads();

    const int ar = tid >> 2, ak = (tid & 3) * 16;   // 96 rows x 64 k staging
    // epilogue node-mix mapping: one row, octet of units per thread
    const int er = tid >> 2, eu = (tid & 3) * 8;
    const int elb = er / NN, en = er - elb * NN;

    // issue a 96x64 chunk WITHOUT commit (caller groups + commits)
    auto issue_nc = [&](const __half* src, int kk, int buf) {
        uint32_t sb = smu + SM_STAGE + buf*BUFB + (ar*ASTR + ak)*2;
        const __half* gp = src + (size_t)(m0 + ar)*256 + kk + ak;
        cp16(sb, gp);
        cp16(sb + 16, gp + 8);
    };
    auto issue = [&](const __half* src, int kk, int buf) {
        issue_nc(src, kk, buf);
        CP_COMMIT();
    };

    // prologue: x0 -> B0, x1 -> B1 (two groups in flight)
    issue(Xh, 0, 0);
    issue(Xh, 64, 1);

    for (int t = 0; t < TT; ++t) {
        const int pi = t & 1, po = pi ^ 1;
        const __half* XhT = Xh + (size_t)t*ROWS*FF;
        const __half* XhN = XhT + ROWS*FF;
        const __half* GhHp = GhH + (size_t)pi*ROWS*HH;
        const bool more = (t + 1 < TT);

        float acc[2][4][4];
        #pragma unroll
        for (int i = 0; i < 2; ++i)
            #pragma unroll
            for (int j = 0; j < 4; ++j)
                #pragma unroll
                for (int e = 0; e < 4; ++e) acc[i][j][e] = 0.f;

        auto compute = [&](int kw, int buf) {   // kw = global k base into sWh
            const __half* sB = (const __half*)(sm + SM_STAGE + buf*BUFB);
            #pragma unroll
            for (int kq = 0; kq < 64; kq += 16) {
                unsigned a[2][4], w[4][2];
                #pragma unroll
                for (int i = 0; i < 2; ++i) {
                    int row = wr*32 + i*16 + (lane & 15);
                    int col = kq + ((lane >> 4) << 3);
                    ldsm4(a[i], &sB[row*ASTR + col]);
                }
                #pragma unroll
                for (int j2 = 0; j2 < 2; ++j2) {
                    int g = lane >> 3, r = lane & 7;
                    int grow = wg*32 + j2*16 + ((g >> 1) << 3) + r;
                    int kcol = kw + kq + ((g & 1) << 3);
                    unsigned tw[4];
                    ldsm4(tw, &sWh[grow*WSTR + kcol]);
                    w[j2*2][0]   = tw[0]; w[j2*2][1]   = tw[1];
                    w[j2*2+1][0] = tw[2]; w[j2*2+1][1] = tw[3];
                }
                #pragma unroll
                for (int i = 0; i < 2; ++i)
                    #pragma unroll
                    for (int j = 0; j < 4; ++j)
                        mma16816(acc[i][j], a[i], w[j]);
            }
        };

        // ---- phase 1: k [0,256) from x(t); x0/x1 already in flight ----
        CP_WAIT1(); __syncthreads(); issue(XhT, 128, 2); compute(0, 0);
        CP_WAIT1(); __syncthreads(); issue(XhT, 192, 3); compute(64, 1);
        CP_WAIT1(); __syncthreads();                      compute(128, 2);
        CP_WAIT0(); __syncthreads();                      compute(192, 3);

        // ---- peer barrier: all 8 CTAs of this row-group published Gh(t) ----
        if (t > 0) {
            if (tid == 0) {
                unsigned v, tgt = 8u * (unsigned)t;
                while (1) {
                    asm volatile("ld.acquire.gpu.global.u32 %0, [%1];"
                                 : "=r"(v) : "l"(&g_bar[grp]) : "memory");
                    if (v >= tgt) break;
                    __nanosleep(32);
                }
            }
            __syncthreads();
        }

        // ---- phase 2: k [256,512) from Gh(t); prefetch next x in d1/d2 ----
        issue(GhHp, 0, 0);
        issue(GhHp, 64, 1);
        CP_WAIT1(); __syncthreads(); issue(GhHp, 128, 2); compute(256, 0);
        CP_WAIT1(); __syncthreads();
        {   // g3 (+ next-step x0) as ONE commit group
            issue_nc(GhHp, 192, 3);
            if (more) issue_nc(XhN, 0, 0);
            CP_COMMIT();
        }
        compute(320, 1);
        CP_WAIT1(); __syncthreads(); if (more) issue(XhN, 64, 1); compute(384, 2);
        if (more) { CP_WAIT1(); } else { CP_WAIT0(); }
        __syncthreads();
        compute(448, 3);

        // ---- fused epilogue: shfl-quad + LSTM cell (c in regs) ----
        #pragma unroll
        for (int i = 0; i < 2; ++i)
            #pragma unroll
            for (int j = 0; j < 4; ++j) {
                float d0 = acc[i][j][0], d1 = acc[i][j][1];
                float d2 = acc[i][j][2], d3 = acc[i][j][3];
                float s0 = __shfl_xor_sync(0xffffffffu, p ? d0 : d2, 1);
                float s1 = __shfl_xor_sync(0xffffffffu, p ? d1 : d3, 1);
                float qi = p ? s0 : d0, qf = p ? s1 : d1;
                float qg = p ? d2 : s0, qo = p ? d3 : s1;
                int row = wr*32 + i*16 + (lane >> 2) + 8*p;
                int uu  = wg*8 + 2*j + ((lane & 3) >> 1);
                float4 bv = *(const float4*)&sBias[4*uu];
                float vi = sigf(qi + bv.x);
                float vf = sigf(qf + bv.y);
                float vg = tanh_fast(qg + bv.z);
                float vo = sigf(qo + bv.w);
                float cv = vf * creg[i*4 + j] + vi * vg;
                creg[i*4 + j] = cv;
                Hs[row*HSTR + uu] = vo * tanh_fast(cv);
            }
        __syncthreads();
        // node-mix fresh h -> Gh(po): one row x 8 units per thread, vectorized
        {
            float4 A = {0.f, 0.f, 0.f, 0.f}, B4 = {0.f, 0.f, 0.f, 0.f};
            const float* gr = &sG[en*NN];
            #pragma unroll
            for (int m = 0; m < NN; ++m) {
                float g = gr[m];
                const float4* hp = (const float4*)&Hs[(elb*NN + m)*HSTR + eu];
                float4 h0 = hp[0], h1 = hp[1];
                A.x += g*h0.x; A.y += g*h0.y; A.z += g*h0.z; A.w += g*h0.w;
                B4.x += g*h1.x; B4.y += g*h1.y; B4.z += g*h1.z; B4.w += g*h1.w;
            }
            uint4 hv;
            hv.x = pack2h(A.x, A.y);  hv.y = pack2h(A.z, A.w);
            hv.z = pack2h(B4.x, B4.y); hv.w = pack2h(B4.z, B4.w);
            size_t off = (size_t)(m0 + er)*HH + u0 + eu;
            *(uint4*)(GhH + (size_t)po*ROWS*HH + off) = hv;
            if (t == TT - 1) {   // lo residual for final fc GEMM
                const __half* hb = (const __half*)&hv;
                float lo[8] = {
                    A.x  - __half2float(hb[0]), A.y  - __half2float(hb[1]),
                    A.z  - __half2float(hb[2]), A.w  - __half2float(hb[3]),
                    B4.x - __half2float(hb[4]), B4.y - __half2float(hb[5]),
                    B4.z - __half2float(hb[6]), B4.w - __half2float(hb[7]) };
                uint4 lv;
                lv.x = pack2h(lo[0], lo[1]); lv.y = pack2h(lo[2], lo[3]);
                lv.z = pack2h(lo[4], lo[5]); lv.w = pack2h(lo[6], lo[7]);
                *(uint4*)(GhL + off) = lv;
            }
        }
        __syncthreads();
        if (tid == 0)
            asm volatile("red.release.gpu.global.add.u32 [%0], %1;"
                         :: "l"(&g_bar[grp]), "r"(1u) : "memory");
    }
}

// ---------------------------------------------------------------------------
extern "C" void kernel_launch(void* const* d_in, const int* in_sizes, int n_in,
                              void* d_out, int out_size)
{
    const float* x    = (const float*)d_in[0];
    const float* G    = (const float*)d_in[1];
    const float* W_ih = (const float*)d_in[2];
    const float* b_ih = (const float*)d_in[3];
    const float* W_hh = (const float*)d_in[4];
    const float* b_hh = (const float*)d_in[5];
    const float* W_h1 = (const float*)d_in[6];
    const float* b_h1 = (const float*)d_in[7];
    const float* W_h2 = (const float*)d_in[8];
    const float* b_h2 = (const float*)d_in[9];
    const float* W_fc = (const float*)d_in[10];
    const float* b_fc = (const float*)d_in[11];
    float* out = (float*)d_out;

    __half *Xh, *Xl, *Ghh, *Ghl, *Wch, *W1h, *W1l, *W2h, *W2l, *Wfh, *Wfl;
    float *bcat, *h, *c;
    cudaGetSymbolAddress((void**)&Xh,  g_Xh);
    cudaGetSymbolAddress((void**)&Xl,  g_Xl);
    cudaGetSymbolAddress((void**)&Ghh, g_Ghh);
    cudaGetSymbolAddress((void**)&Ghl, g_Ghl);
    cudaGetSymbolAddress((void**)&Wch, g_Wch);
    cudaGetSymbolAddress((void**)&W1h, g_W1h);
    cudaGetSymbolAddress((void**)&W1l, g_W1l);
    cudaGetSymbolAddress((void**)&W2h, g_W2h);
    cudaGetSymbolAddress((void**)&W2l, g_W2l);
    cudaGetSymbolAddress((void**)&Wfh, g_Wfh);
    cudaGetSymbolAddress((void**)&Wfl, g_Wfl);
    cudaGetSymbolAddress((void**)&bcat, g_bcat);
    cudaGetSymbolAddress((void**)&h,   g_h);
    cudaGetSymbolAddress((void**)&c,   g_c);

    cudaFuncSetAttribute(lstm_persist, cudaFuncAttributeMaxDynamicSharedMemorySize, SM_TOTAL);

    // prep
    mix_x<<<BB*TT, 256>>>(x, G);
    pack_cat<<<(G4H*KCAT)/256, 256>>>(W_ih, W_hh, b_ih, b_hh);
    pack_all<<<768, 256>>>(W_h1, W_h2, W_fc);

    // h0 and c0 concurrently (z selects weight/bias/output)
    mma_small<0><<<dim3(4, 16, 2), 192>>>(Xh, Xl,
                                          W1h, W1l, b_h1, h,
                                          W2h, W2l, b_h2, c);
    mix_h<<<BB, 256>>>(G, Ghh);   // Gh(0) hi -> buffer 0

    // persistent pure-fp16 scan (50 steps, depth-2 cp.async pipeline)
    lstm_persist<<<128, PTHREADS, SM_TOTAL>>>(Xh, Wch, bcat, G, c, Ghh, Ghl);

    // output: tanh((G h) @ W_fc^T + b_fc); after 50 steps Gh is in buffer 0
    mma_small<1><<<dim3(4, 16, 1), 192>>>(Ghh, Ghl,
                                          Wfh, Wfl, b_fc, out,
                                          Wfh, Wfl, b_fc, out);
}